// round 15
// baseline (speedup 1.0000x reference)
#include <cuda_runtime.h>
#include <math.h>
#include <stdint.h>

#define BATCH 128
#define SEQ   50
#define DIM   512
#define HID   2048
#define VOCAB 32000
#define ROWS  (BATCH*SEQ)   // 6400
#define LN_EPS 1e-5f

// ---------------- scratch (device globals; no allocation) ----------------
__device__ float g_x0  [ROWS*DIM];       // tf32-rounded
__device__ float g_qkv [ROWS*3*DIM];     // fused Q|K|V, row stride 1536
__device__ float g_wqkv[DIM*3*DIM];      // packed + tf32-rounded
__device__ float g_bqkv[3*DIM];
__device__ float g_att [ROWS*DIM];
__device__ float g_x1  [ROWS*DIM];       // tf32-rounded
__device__ float g_h   [ROWS*HID];       // tf32-rounded
__device__ float g_f   [ROWS*DIM];
__device__ float g_x2  [ROWS*DIM];       // tf32-rounded
__device__ float g_w1r [DIM*HID];        // tf32-rounded weights
__device__ float g_w2r [HID*DIM];
__device__ float g_wor [DIM*VOCAB];

// tf32 RNA round, value kept in fp32 (low 13 mantissa bits zero)
__device__ __forceinline__ float rtf(float f) {
    uint32_t o; asm("cvt.rna.tf32.f32 %0, %1;" : "=r"(o) : "f"(f));
    return __uint_as_float(o);
}

// ---------------- generic tf32 pre-round: dst = rna_tf32(src) ----------------
__global__ void round_tf32_kernel(const float* __restrict__ src,
                                  float* __restrict__ dst, int n4)
{
    int stride = gridDim.x * blockDim.x;
    for (int i = blockIdx.x * blockDim.x + threadIdx.x; i < n4; i += stride) {
        float4 v = ((const float4*)src)[i];
        ((float4*)dst)[i] = make_float4(rtf(v.x), rtf(v.y), rtf(v.z), rtf(v.w));
    }
}

// ---------------- embed: x = rtf(emb[idx] + pos) ----------------
__global__ void embed_kernel(const int* __restrict__ idx,
                             const float* __restrict__ emb,
                             const float* __restrict__ pos,
                             float* __restrict__ x)
{
    int row = blockIdx.x;
    int s   = row % SEQ;
    int tok = idx[row];
    const float4* e = (const float4*)(emb + (size_t)tok * DIM);
    const float4* p = (const float4*)(pos + (size_t)s   * DIM);
    float4*       o = (float4*)(x + (size_t)row * DIM);
    for (int i = threadIdx.x; i < DIM/4; i += blockDim.x) {
        float4 a = e[i], b = p[i];
        o[i] = make_float4(rtf(a.x+b.x), rtf(a.y+b.y), rtf(a.z+b.z), rtf(a.w+b.w));
    }
}

// ---------------- pack wq|wk|wv -> [512][1536] (tf32-rounded) ----------------
__global__ void pack_qkv_kernel(const float* __restrict__ wq, const float* __restrict__ wk,
                                const float* __restrict__ wv, const float* __restrict__ bq,
                                const float* __restrict__ bk, const float* __restrict__ bv,
                                float* __restrict__ wqkv, float* __restrict__ bqkv)
{
    int k = blockIdx.x;                     // 0..511
    float4* dst = (float4*)(wqkv + (size_t)k * 1536);
    const float4* q  = (const float4*)(wq + (size_t)k * DIM);
    const float4* kk = (const float4*)(wk + (size_t)k * DIM);
    const float4* v  = (const float4*)(wv + (size_t)k * DIM);
    for (int i = threadIdx.x; i < DIM/4; i += blockDim.x) {
        float4 a = q[i];
        dst[i]         = make_float4(rtf(a.x), rtf(a.y), rtf(a.z), rtf(a.w));
        a = kk[i];
        dst[i + DIM/4] = make_float4(rtf(a.x), rtf(a.y), rtf(a.z), rtf(a.w));
        a = v[i];
        dst[i + DIM/2] = make_float4(rtf(a.x), rtf(a.y), rtf(a.z), rtf(a.w));
    }
    if (k == 0) {
        for (int i = threadIdx.x; i < DIM; i += blockDim.x) {
            bqkv[i]         = bq[i];
            bqkv[i + DIM]   = bk[i];
            bqkv[i + 2*DIM] = bv[i];
        }
    }
}

// ---------------- tf32 tensor-core GEMM, 2-stage cp.async pipeline ------------
// C = act(A[M,K] @ W[K,N] + bias).  Inputs PRE-ROUNDED to tf32 values, so the
// mainloop feeds raw bits to mma.tf32 (HW truncation = identity): pure LDS+MMA.
// BM=128, BN=256, BK=32, 256 threads = 8 warps (2 M x 4 N), warp tile 64x64.
// ACT: 0 none, 2 exact gelu (output re-rounded for next GEMM), 3 qkv-mix.
#define STG_F (128*36 + 32*264)      // 13056 floats per stage
#define SMEM_BYTES (2 * STG_F * 4)   // 104448

__device__ __forceinline__ void cp_async16(uint32_t dst, const void* src) {
    asm volatile("cp.async.cg.shared.global [%0], [%1], 16;\n" :: "r"(dst), "l"(src));
}

template<int ACT>
__global__ __launch_bounds__(256) void gemm_tf32_pipe(
    const float* __restrict__ A, const float* __restrict__ W,
    const float* __restrict__ bias, float* __restrict__ C,
    int M, int N, int K)
{
    extern __shared__ float sm[];

    int tid  = threadIdx.x;
    int warp = tid >> 5, lane = tid & 31;
    int wm = warp >> 2, wn = warp & 3;
    int gid = lane >> 2, tig = lane & 3;
    int bm = blockIdx.y * 128, bn = blockIdx.x * 256;

    uint32_t smem_u32;
    asm("{ .reg .u64 t; cvta.to.shared.u64 t, %1; cvt.u32.u64 %0, t; }"
        : "=r"(smem_u32) : "l"(sm));

    float acc[4][8][4];
    #pragma unroll
    for (int i = 0; i < 4; i++)
        #pragma unroll
        for (int j = 0; j < 8; j++)
            #pragma unroll
            for (int c = 0; c < 4; c++) acc[i][j][c] = 0.f;

    const int T = K / 32;

    auto issue = [&](int t) {
        int kt = t * 32;
        uint32_t base = smem_u32 + (uint32_t)(t & 1) * (STG_F * 4);
        #pragma unroll
        for (int r = 0; r < 4; r++) {
            int q  = tid + r * 256;
            int m  = q >> 3;
            int k4 = (q & 7) * 4;
            cp_async16(base + (uint32_t)(m * 36 + k4) * 4,
                       A + (size_t)(bm + m) * K + kt + k4);
        }
        #pragma unroll
        for (int r = 0; r < 8; r++) {
            int q  = tid + r * 256;
            int k  = q >> 6;
            int n4 = (q & 63) * 4;
            cp_async16(base + (uint32_t)(128*36 + k * 264 + n4) * 4,
                       W + (size_t)(kt + k) * N + bn + n4);
        }
        asm volatile("cp.async.commit_group;\n" ::);
    };

    issue(0);

    for (int t = 0; t < T; t++) {
        if (t + 1 < T) {
            issue(t + 1);
            asm volatile("cp.async.wait_group 1;\n" ::);
        } else {
            asm volatile("cp.async.wait_group 0;\n" ::);
        }
        __syncthreads();

        const uint32_t* As_ = (const uint32_t*)(sm + (t & 1) * STG_F);
        const uint32_t* Bs_ = As_ + 128*36;

        #pragma unroll
        for (int kk = 0; kk < 32; kk += 8) {
            uint32_t af[4][4], bf[8][2];
            #pragma unroll
            for (int mt = 0; mt < 4; mt++) {
                int m0 = wm * 64 + mt * 16;
                af[mt][0] = As_[(m0 + gid    ) * 36 + kk + tig    ];
                af[mt][1] = As_[(m0 + gid + 8) * 36 + kk + tig    ];
                af[mt][2] = As_[(m0 + gid    ) * 36 + kk + tig + 4];
                af[mt][3] = As_[(m0 + gid + 8) * 36 + kk + tig + 4];
            }
            #pragma unroll
            for (int nt = 0; nt < 8; nt++) {
                int n0 = wn * 64 + nt * 8;
                bf[nt][0] = Bs_[(kk + tig    ) * 264 + n0 + gid];
                bf[nt][1] = Bs_[(kk + tig + 4) * 264 + n0 + gid];
            }
            #pragma unroll
            for (int mt = 0; mt < 4; mt++)
                #pragma unroll
                for (int nt = 0; nt < 8; nt++) {
                    asm volatile(
                        "mma.sync.aligned.m16n8k8.row.col.f32.tf32.tf32.f32 "
                        "{%0,%1,%2,%3}, {%4,%5,%6,%7}, {%8,%9}, {%0,%1,%2,%3};"
                        : "+f"(acc[mt][nt][0]), "+f"(acc[mt][nt][1]),
                          "+f"(acc[mt][nt][2]), "+f"(acc[mt][nt][3])
                        : "r"(af[mt][0]), "r"(af[mt][1]), "r"(af[mt][2]), "r"(af[mt][3]),
                          "r"(bf[nt][0]), "r"(bf[nt][1]));
                }
        }
        __syncthreads();
    }

    #pragma unroll
    for (int mt = 0; mt < 4; mt++) {
        int m = bm + wm * 64 + mt * 16 + gid;
        #pragma unroll
        for (int nt = 0; nt < 8; nt++) {
            int n = bn + wn * 64 + nt * 8 + 2 * tig;
            float b0 = bias[n], b1 = bias[n + 1];
            float v00 = acc[mt][nt][0] + b0, v01 = acc[mt][nt][1] + b1;
            float v10 = acc[mt][nt][2] + b0, v11 = acc[mt][nt][3] + b1;
            if (ACT == 2) {
                // gelu, then round for the next GEMM (FFN2 consumes h)
                v00 = rtf(0.5f * v00 * (1.0f + erff(v00 * 0.70710678118654752f)));
                v01 = rtf(0.5f * v01 * (1.0f + erff(v01 * 0.70710678118654752f)));
                v10 = rtf(0.5f * v10 * (1.0f + erff(v10 * 0.70710678118654752f)));
                v11 = rtf(0.5f * v11 * (1.0f + erff(v11 * 0.70710678118654752f)));
            } else if (ACT == 3) {
                if (n < 2*DIM) {
                    v00 = 1.0f / (1.0f + expf(-v00));
                    v01 = 1.0f / (1.0f + expf(-v01));
                    v10 = 1.0f / (1.0f + expf(-v10));
                    v11 = 1.0f / (1.0f + expf(-v11));
                }
            }
            *(float2*)(C + (size_t)m       * N + n) = make_float2(v00, v01);
            *(float2*)(C + (size_t)(m + 8) * N + n) = make_float2(v10, v11);
        }
    }
}

// ---------------- attention (fused QKV layout, row stride 1536) --------------
__global__ __launch_bounds__(128) void attn_kernel(
    const float* __restrict__ QKV, float* __restrict__ O)
{
    int row = blockIdx.x;
    int b = row / SEQ, i = row % SEQ;
    int tid = threadIdx.x, warp = tid >> 5, lane = tid & 31;

    __shared__ float sQ[DIM];
    __shared__ float sp[SEQ];

    const float* q = QKV + (size_t)row * (3*DIM);
    for (int d = tid; d < DIM; d += 128) sQ[d] = q[d];
    __syncthreads();

    for (int j = warp; j < SEQ; j += 4) {
        float s = 0.f;
        if (j <= i) {
            const float* kp = QKV + ((size_t)b * SEQ + j) * (3*DIM) + DIM;
            for (int d = lane; d < DIM; d += 32)
                s += fminf(1.0f - sQ[d] + kp[d], 1.0f);
            #pragma unroll
            for (int o = 16; o; o >>= 1) s += __shfl_xor_sync(0xffffffffu, s, o);
            s *= (10.0f / (float)DIM);
        }
        if (lane == 0) sp[j] = s;
    }
    __syncthreads();

    if (warp == 0) {
        float m = -1e30f;
        for (int j = lane; j < SEQ; j += 32) m = fmaxf(m, sp[j]);
        #pragma unroll
        for (int o = 16; o; o >>= 1) m = fmaxf(m, __shfl_xor_sync(0xffffffffu, m, o));
        float sum = 0.f;
        float e0 = 0.f, e1 = 0.f;
        if (lane      < SEQ) { e0 = expf(sp[lane]      - m); sum += e0; }
        if (lane + 32 < SEQ) { e1 = expf(sp[lane + 32] - m); sum += e1; }
        #pragma unroll
        for (int o = 16; o; o >>= 1) sum += __shfl_xor_sync(0xffffffffu, sum, o);
        float inv = 1.0f / sum;
        if (lane      < SEQ) sp[lane]      = e0 * inv;
        if (lane + 32 < SEQ) sp[lane + 32] = e1 * inv;
    }
    __syncthreads();

    float acc[4] = {0.f, 0.f, 0.f, 0.f};
    for (int j = 0; j < SEQ; j++) {
        float p = sp[j];
        const float* v = QKV + ((size_t)b * SEQ + j) * (3*DIM) + 2*DIM;
        #pragma unroll
        for (int u = 0; u < 4; u++) acc[u] += p * v[tid + u*128];
    }
    float* o = O + (size_t)row * DIM;
    #pragma unroll
    for (int u = 0; u < 4; u++) o[tid + u*128] = acc[u];
}

// ---------------- fused residual add + LayerNorm (output tf32-rounded) -------
__global__ __launch_bounds__(128) void add_ln_kernel(
    const float* __restrict__ a, const float* __restrict__ r,
    const float* __restrict__ g, const float* __restrict__ be,
    float* __restrict__ out)
{
    int row = blockIdx.x, tid = threadIdx.x;
    const float* pa = a + (size_t)row * DIM;
    const float* pr = r + (size_t)row * DIM;

    float v[4];
    float sum = 0.f;
    #pragma unroll
    for (int u = 0; u < 4; u++) {
        int d = tid + u*128;
        v[u] = pa[d] + pr[d];
        sum += v[u];
    }
    __shared__ float red[4];
    #pragma unroll
    for (int o = 16; o; o >>= 1) sum += __shfl_xor_sync(0xffffffffu, sum, o);
    if ((tid & 31) == 0) red[tid >> 5] = sum;
    __syncthreads();
    float mean = (red[0] + red[1] + red[2] + red[3]) * (1.0f / DIM);

    float vs = 0.f;
    #pragma unroll
    for (int u = 0; u < 4; u++) { float d = v[u] - mean; vs += d * d; }
    #pragma unroll
    for (int o = 16; o; o >>= 1) vs += __shfl_xor_sync(0xffffffffu, vs, o);
    __shared__ float red2[4];
    if ((tid & 31) == 0) red2[tid >> 5] = vs;
    __syncthreads();
    float var = (red2[0] + red2[1] + red2[2] + red2[3]) * (1.0f / DIM);
    float inv = rsqrtf(var + LN_EPS);

    float* po = out + (size_t)row * DIM;
    #pragma unroll
    for (int u = 0; u < 4; u++) {
        int d = tid + u*128;
        po[d] = rtf((v[u] - mean) * inv * g[d] + be[d]);
    }
}

// ---------------- launch ----------------
extern "C" void kernel_launch(void* const* d_in, const int* in_sizes, int n_in,
                              void* d_out, int out_size)
{
    const int*   idx = (const int*)  d_in[0];
    const float* emb = (const float*)d_in[1];
    const float* pos = (const float*)d_in[2];
    const float* wq  = (const float*)d_in[3];
    const float* bq  = (const float*)d_in[4];
    const float* wk  = (const float*)d_in[5];
    const float* bk  = (const float*)d_in[6];
    const float* wv  = (const float*)d_in[7];
    const float* bv  = (const float*)d_in[8];
    const float* w1  = (const float*)d_in[9];
    const float* b1  = (const float*)d_in[10];
    const float* w2  = (const float*)d_in[11];
    const float* b2  = (const float*)d_in[12];
    const float* g1  = (const float*)d_in[13];
    const float* be1 = (const float*)d_in[14];
    const float* g2  = (const float*)d_in[15];
    const float* be2 = (const float*)d_in[16];
    const float* wo  = (const float*)d_in[17];
    const float* bo  = (const float*)d_in[18];
    float* out = (float*)d_out;

    float *x0, *qkv, *wqkv, *bqkv, *att, *x1, *h, *f, *x2, *w1r, *w2r, *wor;
    cudaGetSymbolAddress((void**)&x0,   g_x0);
    cudaGetSymbolAddress((void**)&qkv,  g_qkv);
    cudaGetSymbolAddress((void**)&wqkv, g_wqkv);
    cudaGetSymbolAddress((void**)&bqkv, g_bqkv);
    cudaGetSymbolAddress((void**)&att,  g_att);
    cudaGetSymbolAddress((void**)&x1,   g_x1);
    cudaGetSymbolAddress((void**)&h,    g_h);
    cudaGetSymbolAddress((void**)&f,    g_f);
    cudaGetSymbolAddress((void**)&x2,   g_x2);
    cudaGetSymbolAddress((void**)&w1r,  g_w1r);
    cudaGetSymbolAddress((void**)&w2r,  g_w2r);
    cudaGetSymbolAddress((void**)&wor,  g_wor);

    cudaFuncSetAttribute(gemm_tf32_pipe<0>, cudaFuncAttributeMaxDynamicSharedMemorySize, SMEM_BYTES);
    cudaFuncSetAttribute(gemm_tf32_pipe<2>, cudaFuncAttributeMaxDynamicSharedMemorySize, SMEM_BYTES);
    cudaFuncSetAttribute(gemm_tf32_pipe<3>, cudaFuncAttributeMaxDynamicSharedMemorySize, SMEM_BYTES);

    // 1. embed (rounded) + weight pre-rounding
    embed_kernel<<<ROWS, 128>>>(idx, emb, pos, x0);
    pack_qkv_kernel<<<DIM, 128>>>(wq, wk, wv, bq, bk, bv, wqkv, bqkv);
    round_tf32_kernel<<<1024, 256>>>(w1, w1r, DIM*HID/4);
    round_tf32_kernel<<<1024, 256>>>(w2, w2r, HID*DIM/4);
    round_tf32_kernel<<<8192, 256>>>(wo, wor, DIM*VOCAB/4);

    // 2. fused QKV projection (sigmoid on Q,K columns)
    dim3 blk(256);
    dim3 g_qkvd(3*DIM/256, ROWS/128);   // (6, 50)
    gemm_tf32_pipe<3><<<g_qkvd, blk, SMEM_BYTES>>>(x0, wqkv, bqkv, qkv, ROWS, 3*DIM, DIM);

    // 3. Lukasiewicz attention
    attn_kernel<<<ROWS, 128>>>(qkv, att);

    // 4. LN1(x0 + att) -> rounded x1
    add_ln_kernel<<<ROWS, 128>>>(x0, att, g1, be1, x1);

    // 5. FFN (gelu fused + rounded h)
    dim3 g_h1(HID/256, ROWS/128);       // (8, 50)
    dim3 g_d(DIM/256, ROWS/128);        // (2, 50)
    gemm_tf32_pipe<2><<<g_h1, blk, SMEM_BYTES>>>(x1, w1r, b1, h, ROWS, HID, DIM);
    gemm_tf32_pipe<0><<<g_d,  blk, SMEM_BYTES>>>(h,  w2r, b2, f, ROWS, DIM, HID);

    // 6. LN2(x1 + f) -> rounded x2
    add_ln_kernel<<<ROWS, 128>>>(x1, f, g2, be2, x2);

    // 7. output projection -> d_out
    dim3 g_o(VOCAB/256, ROWS/128);      // (125, 50)
    gemm_tf32_pipe<0><<<g_o, blk, SMEM_BYTES>>>(x2, wor, bo, out, ROWS, VOCAB, DIM);
}

// round 17
// speedup vs baseline: 1.3848x; 1.3848x over previous
#include <cuda_runtime.h>
#include <math.h>
#include <stdint.h>

#define BATCH 128
#define SEQ   50
#define DIM   512
#define HID   2048
#define VOCAB 32000
#define ROWS  (BATCH*SEQ)   // 6400
#define LN_EPS 1e-5f

// ---------------- scratch (device globals; no allocation) ----------------
__device__ float g_x0[ROWS*DIM];
__device__ float g_Q [ROWS*DIM];
__device__ float g_K [ROWS*DIM];
__device__ float g_V [ROWS*DIM];
__device__ float g_att[ROWS*DIM];
__device__ float g_x1[ROWS*DIM];
__device__ float g_h [ROWS*HID];
__device__ float g_f [ROWS*DIM];
__device__ float g_x2[ROWS*DIM];

// ---------------- embed: x = emb[idx] + pos ----------------
__global__ void embed_kernel(const int* __restrict__ idx,
                             const float* __restrict__ emb,
                             const float* __restrict__ pos,
                             float* __restrict__ x)
{
    int row = blockIdx.x;
    int s   = row % SEQ;
    int tok = idx[row];
    const float4* e = (const float4*)(emb + (size_t)tok * DIM);
    const float4* p = (const float4*)(pos + (size_t)s   * DIM);
    float4*       o = (float4*)(x + (size_t)row * DIM);
    for (int i = threadIdx.x; i < DIM/4; i += blockDim.x) {
        float4 a = e[i], b = p[i];
        o[i] = make_float4(a.x+b.x, a.y+b.y, a.z+b.z, a.w+b.w);
    }
}

// ---------------- tf32 tensor-core GEMM, 2-stage cp.async pipeline ------------
// EXACT R8 mainloop (best measured).  BM=128, BN=256, BK=32, 256 threads =
// 8 warps (2 M x 4 N), warp tile 64x64, cvt.rna.tf32 after fragment LDS.
// NEW in R16: smem-staged coalesced epilogue (two 64-row halves through the
// pipeline smem buffer; scatter w/ bias+act, then float4 row-major stores).
// ACT: 0 none, 1 sigmoid, 2 exact gelu.
#define STG_F (128*36 + 32*264)      // 13056 floats per stage
#define SMEM_BYTES (2 * STG_F * 4)   // 104448

__device__ __forceinline__ void cp_async16(uint32_t dst, const void* src) {
    asm volatile("cp.async.cg.shared.global [%0], [%1], 16;\n" :: "r"(dst), "l"(src));
}
__device__ __forceinline__ uint32_t f2tf32(float f) {
    uint32_t o;
    asm("cvt.rna.tf32.f32 %0, %1;" : "=r"(o) : "f"(f));
    return o;
}

template<int ACT>
__global__ __launch_bounds__(256) void gemm_tf32_pipe(
    const float* __restrict__ A, const float* __restrict__ W,
    const float* __restrict__ bias, float* __restrict__ C,
    int M, int N, int K)
{
    extern __shared__ float sm[];

    int tid  = threadIdx.x;
    int warp = tid >> 5, lane = tid & 31;
    int wm = warp >> 2, wn = warp & 3;
    int gid = lane >> 2, tig = lane & 3;
    int bm = blockIdx.y * 128, bn = blockIdx.x * 256;

    uint32_t smem_u32;
    asm("{ .reg .u64 t; cvta.to.shared.u64 t, %1; cvt.u32.u64 %0, t; }"
        : "=r"(smem_u32) : "l"(sm));

    float acc[4][8][4];
    #pragma unroll
    for (int i = 0; i < 4; i++)
        #pragma unroll
        for (int j = 0; j < 8; j++)
            #pragma unroll
            for (int c = 0; c < 4; c++) acc[i][j][c] = 0.f;

    const int T = K / 32;

    auto issue = [&](int t) {
        int kt = t * 32;
        uint32_t base = smem_u32 + (uint32_t)(t & 1) * (STG_F * 4);
        #pragma unroll
        for (int r = 0; r < 4; r++) {
            int q  = tid + r * 256;
            int m  = q >> 3;
            int k4 = (q & 7) * 4;
            cp_async16(base + (uint32_t)(m * 36 + k4) * 4,
                       A + (size_t)(bm + m) * K + kt + k4);
        }
        #pragma unroll
        for (int r = 0; r < 8; r++) {
            int q  = tid + r * 256;
            int k  = q >> 6;
            int n4 = (q & 63) * 4;
            cp_async16(base + (uint32_t)(128*36 + k * 264 + n4) * 4,
                       W + (size_t)(kt + k) * N + bn + n4);
        }
        asm volatile("cp.async.commit_group;\n" ::);
    };

    issue(0);

    for (int t = 0; t < T; t++) {
        if (t + 1 < T) {
            issue(t + 1);
            asm volatile("cp.async.wait_group 1;\n" ::);
        } else {
            asm volatile("cp.async.wait_group 0;\n" ::);
        }
        __syncthreads();

        const float* As_ = sm + (t & 1) * STG_F;
        const float* Bs_ = As_ + 128*36;

        #pragma unroll
        for (int kk = 0; kk < 32; kk += 8) {
            uint32_t af[4][4], bf[8][2];
            #pragma unroll
            for (int mt = 0; mt < 4; mt++) {
                int m0 = wm * 64 + mt * 16;
                af[mt][0] = f2tf32(As_[(m0 + gid    ) * 36 + kk + tig    ]);
                af[mt][1] = f2tf32(As_[(m0 + gid + 8) * 36 + kk + tig    ]);
                af[mt][2] = f2tf32(As_[(m0 + gid    ) * 36 + kk + tig + 4]);
                af[mt][3] = f2tf32(As_[(m0 + gid + 8) * 36 + kk + tig + 4]);
            }
            #pragma unroll
            for (int nt = 0; nt < 8; nt++) {
                int n0 = wn * 64 + nt * 8;
                bf[nt][0] = f2tf32(Bs_[(kk + tig    ) * 264 + n0 + gid]);
                bf[nt][1] = f2tf32(Bs_[(kk + tig + 4) * 264 + n0 + gid]);
            }
            #pragma unroll
            for (int mt = 0; mt < 4; mt++)
                #pragma unroll
                for (int nt = 0; nt < 8; nt++) {
                    asm volatile(
                        "mma.sync.aligned.m16n8k8.row.col.f32.tf32.tf32.f32 "
                        "{%0,%1,%2,%3}, {%4,%5,%6,%7}, {%8,%9}, {%0,%1,%2,%3};"
                        : "+f"(acc[mt][nt][0]), "+f"(acc[mt][nt][1]),
                          "+f"(acc[mt][nt][2]), "+f"(acc[mt][nt][3])
                        : "r"(af[mt][0]), "r"(af[mt][1]), "r"(af[mt][2]), "r"(af[mt][3]),
                          "r"(bf[nt][0]), "r"(bf[nt][1]));
                }
        }
        __syncthreads();
    }

    // ---- smem-staged coalesced epilogue (two 64-row halves) ----
    // half h covers mt = 2h+j (j=0,1): local row rl = wm*32 + j*16 + gid (+8),
    // global row m = bm + 32*h + rl + 32*(rl>>5).
    float* buf = sm;   // pipeline done; reuse (needs 64*264 floats = 67.6 KB)
    #pragma unroll
    for (int h = 0; h < 2; h++) {
        __syncthreads();
        #pragma unroll
        for (int j = 0; j < 2; j++) {
            int mt = 2*h + j;
            int rl0 = wm * 32 + j * 16 + gid;
            #pragma unroll
            for (int nt = 0; nt < 8; nt++) {
                int nl = wn * 64 + nt * 8 + 2 * tig;
                int n  = bn + nl;
                float b0 = bias[n], b1 = bias[n + 1];
                float v00 = acc[mt][nt][0] + b0, v01 = acc[mt][nt][1] + b1;
                float v10 = acc[mt][nt][2] + b0, v11 = acc[mt][nt][3] + b1;
                if (ACT == 1) {
                    v00 = 1.0f / (1.0f + expf(-v00));
                    v01 = 1.0f / (1.0f + expf(-v01));
                    v10 = 1.0f / (1.0f + expf(-v10));
                    v11 = 1.0f / (1.0f + expf(-v11));
                } else if (ACT == 2) {
                    v00 = 0.5f * v00 * (1.0f + erff(v00 * 0.70710678118654752f));
                    v01 = 0.5f * v01 * (1.0f + erff(v01 * 0.70710678118654752f));
                    v10 = 0.5f * v10 * (1.0f + erff(v10 * 0.70710678118654752f));
                    v11 = 0.5f * v11 * (1.0f + erff(v11 * 0.70710678118654752f));
                }
                *(float2*)&buf[(size_t)rl0       * 264 + nl] = make_float2(v00, v01);
                *(float2*)&buf[(size_t)(rl0 + 8) * 264 + nl] = make_float2(v10, v11);
            }
        }
        __syncthreads();
        // coalesced copy: 64 rows x 256 floats = 4096 float4, 16 per thread
        #pragma unroll
        for (int r = 0; r < 16; r++) {
            int q  = tid + r * 256;
            int rl = q >> 6;
            int c4 = (q & 63) * 4;
            int m  = bm + 32*h + rl + 32*(rl >> 5);
            float4 v = *(float4*)&buf[rl * 264 + c4];
            *(float4*)(C + (size_t)m * N + bn + c4) = v;
        }
    }
}

// ---------------- attention ----------------
__global__ __launch_bounds__(128) void attn_kernel(
    const float* __restrict__ Q, const float* __restrict__ K,
    const float* __restrict__ V, float* __restrict__ O)
{
    int row = blockIdx.x;
    int b = row / SEQ, i = row % SEQ;
    int tid = threadIdx.x, warp = tid >> 5, lane = tid & 31;

    __shared__ float sQ[DIM];
    __shared__ float sp[SEQ];

    const float* q = Q + (size_t)row * DIM;
    for (int d = tid; d < DIM; d += 128) sQ[d] = q[d];
    __syncthreads();

    for (int j = warp; j < SEQ; j += 4) {
        float s = 0.f;
        if (j <= i) {
            const float* kp = K + ((size_t)b * SEQ + j) * DIM;
            for (int d = lane; d < DIM; d += 32)
                s += fminf(1.0f - sQ[d] + kp[d], 1.0f);
            #pragma unroll
            for (int o = 16; o; o >>= 1) s += __shfl_xor_sync(0xffffffffu, s, o);
            s *= (10.0f / (float)DIM);
        }
        if (lane == 0) sp[j] = s;
    }
    __syncthreads();

    if (warp == 0) {
        float m = -1e30f;
        for (int j = lane; j < SEQ; j += 32) m = fmaxf(m, sp[j]);
        #pragma unroll
        for (int o = 16; o; o >>= 1) m = fmaxf(m, __shfl_xor_sync(0xffffffffu, m, o));
        float sum = 0.f;
        float e0 = 0.f, e1 = 0.f;
        if (lane      < SEQ) { e0 = expf(sp[lane]      - m); sum += e0; }
        if (lane + 32 < SEQ) { e1 = expf(sp[lane + 32] - m); sum += e1; }
        #pragma unroll
        for (int o = 16; o; o >>= 1) sum += __shfl_xor_sync(0xffffffffu, sum, o);
        float inv = 1.0f / sum;
        if (lane      < SEQ) sp[lane]      = e0 * inv;
        if (lane + 32 < SEQ) sp[lane + 32] = e1 * inv;
    }
    __syncthreads();

    float acc[4] = {0.f, 0.f, 0.f, 0.f};
    for (int j = 0; j < SEQ; j++) {
        float p = sp[j];
        const float* v = V + ((size_t)b * SEQ + j) * DIM;
        #pragma unroll
        for (int u = 0; u < 4; u++) acc[u] += p * v[tid + u*128];
    }
    float* o = O + (size_t)row * DIM;
    #pragma unroll
    for (int u = 0; u < 4; u++) o[tid + u*128] = acc[u];
}

// ---------------- fused residual add + LayerNorm ----------------
__global__ __launch_bounds__(128) void add_ln_kernel(
    const float* __restrict__ a, const float* __restrict__ r,
    const float* __restrict__ g, const float* __restrict__ be,
    float* __restrict__ out)
{
    int row = blockIdx.x, tid = threadIdx.x;
    const float* pa = a + (size_t)row * DIM;
    const float* pr = r + (size_t)row * DIM;

    float v[4];
    float sum = 0.f;
    #pragma unroll
    for (int u = 0; u < 4; u++) {
        int d = tid + u*128;
        v[u] = pa[d] + pr[d];
        sum += v[u];
    }
    __shared__ float red[4];
    #pragma unroll
    for (int o = 16; o; o >>= 1) sum += __shfl_xor_sync(0xffffffffu, sum, o);
    if ((tid & 31) == 0) red[tid >> 5] = sum;
    __syncthreads();
    float mean = (red[0] + red[1] + red[2] + red[3]) * (1.0f / DIM);

    float vs = 0.f;
    #pragma unroll
    for (int u = 0; u < 4; u++) { float d = v[u] - mean; vs += d * d; }
    #pragma unroll
    for (int o = 16; o; o >>= 1) vs += __shfl_xor_sync(0xffffffffu, vs, o);
    __shared__ float red2[4];
    if ((tid & 31) == 0) red2[tid >> 5] = vs;
    __syncthreads();
    float var = (red2[0] + red2[1] + red2[2] + red2[3]) * (1.0f / DIM);
    float inv = rsqrtf(var + LN_EPS);

    float* po = out + (size_t)row * DIM;
    #pragma unroll
    for (int u = 0; u < 4; u++) {
        int d = tid + u*128;
        po[d] = (v[u] - mean) * inv * g[d] + be[d];
    }
}

// ---------------- launch ----------------
extern "C" void kernel_launch(void* const* d_in, const int* in_sizes, int n_in,
                              void* d_out, int out_size)
{
    const int*   idx = (const int*)  d_in[0];
    const float* emb = (const float*)d_in[1];
    const float* pos = (const float*)d_in[2];
    const float* wq  = (const float*)d_in[3];
    const float* bq  = (const float*)d_in[4];
    const float* wk  = (const float*)d_in[5];
    const float* bk  = (const float*)d_in[6];
    const float* wv  = (const float*)d_in[7];
    const float* bv  = (const float*)d_in[8];
    const float* w1  = (const float*)d_in[9];
    const float* b1  = (const float*)d_in[10];
    const float* w2  = (const float*)d_in[11];
    const float* b2  = (const float*)d_in[12];
    const float* g1  = (const float*)d_in[13];
    const float* be1 = (const float*)d_in[14];
    const float* g2  = (const float*)d_in[15];
    const float* be2 = (const float*)d_in[16];
    const float* wo  = (const float*)d_in[17];
    const float* bo  = (const float*)d_in[18];
    float* out = (float*)d_out;

    float *x0, *Qb, *Kb, *Vb, *att, *x1, *h, *f, *x2;
    cudaGetSymbolAddress((void**)&x0,  g_x0);
    cudaGetSymbolAddress((void**)&Qb,  g_Q);
    cudaGetSymbolAddress((void**)&Kb,  g_K);
    cudaGetSymbolAddress((void**)&Vb,  g_V);
    cudaGetSymbolAddress((void**)&att, g_att);
    cudaGetSymbolAddress((void**)&x1,  g_x1);
    cudaGetSymbolAddress((void**)&h,   g_h);
    cudaGetSymbolAddress((void**)&f,   g_f);
    cudaGetSymbolAddress((void**)&x2,  g_x2);

    cudaFuncSetAttribute(gemm_tf32_pipe<0>, cudaFuncAttributeMaxDynamicSharedMemorySize, SMEM_BYTES);
    cudaFuncSetAttribute(gemm_tf32_pipe<1>, cudaFuncAttributeMaxDynamicSharedMemorySize, SMEM_BYTES);
    cudaFuncSetAttribute(gemm_tf32_pipe<2>, cudaFuncAttributeMaxDynamicSharedMemorySize, SMEM_BYTES);

    // 1. embed
    embed_kernel<<<ROWS, 128>>>(idx, emb, pos, x0);

    // 2. Q,K,V projections (tf32; sigmoid fused for Q,K)
    dim3 blk(256);
    dim3 g_d(DIM/256, ROWS/128);       // (2, 50)
    gemm_tf32_pipe<1><<<g_d, blk, SMEM_BYTES>>>(x0, wq, bq, Qb, ROWS, DIM, DIM);
    gemm_tf32_pipe<1><<<g_d, blk, SMEM_BYTES>>>(x0, wk, bk, Kb, ROWS, DIM, DIM);
    gemm_tf32_pipe<0><<<g_d, blk, SMEM_BYTES>>>(x0, wv, bv, Vb, ROWS, DIM, DIM);

    // 3. Lukasiewicz attention
    attn_kernel<<<ROWS, 128>>>(Qb, Kb, Vb, att);

    // 4. LN1(x0 + att)
    add_ln_kernel<<<ROWS, 128>>>(x0, att, g1, be1, x1);

    // 5. FFN (tf32, gelu fused)
    dim3 g_h1(HID/256, ROWS/128);      // (8, 50)
    gemm_tf32_pipe<2><<<g_h1, blk, SMEM_BYTES>>>(x1, w1, b1, h, ROWS, HID, DIM);
    gemm_tf32_pipe<0><<<g_d,  blk, SMEM_BYTES>>>(h,  w2, b2, f, ROWS, DIM, HID);

    // 6. LN2(x1 + f)
    add_ln_kernel<<<ROWS, 128>>>(x1, f, g2, be2, x2);

    // 7. output projection -> d_out (tf32)
    dim3 g_o(VOCAB/256, ROWS/128);     // (125, 50)
    gemm_tf32_pipe<0><<<g_o, blk, SMEM_BYTES>>>(x2, wo, bo, out, ROWS, VOCAB, DIM);
}